// round 1
// baseline (speedup 1.0000x reference)
#include <cuda_runtime.h>
#include <math.h>

#define T  1024
#define Hd 1024
#define Fd 2048
#define Ed 8

#define TM 64
#define TN 64
#define TK 16

// ---------------- scratch (device globals; no runtime allocation) ----------
__device__ float g_inter[(size_t)Ed * T * Fd];  // 64 MB: padded per-expert inter activations
__device__ int   g_tok[Ed * T];                 // token index per expert slot
__device__ float g_pw[Ed * T];                  // routing weight per expert slot
__device__ int   g_cnt[Ed];                     // tokens per expert
__device__ int   g_sel[T * 2];                  // top-2 expert ids per token
__device__ float g_mult[T * 2];                 // top-2 multipliers per token

// ---------------- kernel 0: zero output accumulator + counters -------------
__global__ void zero_kernel(float* __restrict__ out) {
    int i = blockIdx.x * 256 + threadIdx.x;   // grid covers exactly T*Hd
    out[i] = 0.0f;
    if (i < Ed) g_cnt[i] = 0;
}

// ---------------- kernel 1: router GEMV + sparsemixer (eval path) ----------
__global__ __launch_bounds__(256) void router_kernel(
    const float* __restrict__ x, const float* __restrict__ gw,
    float* __restrict__ out_logits, int write_logits)
{
    int t    = blockIdx.x;
    int warp = threadIdx.x >> 5;      // 8 warps = 8 experts
    int lane = threadIdx.x & 31;

    const float* xr = x  + (size_t)t * Hd;
    const float* gr = gw + (size_t)warp * Hd;
    float s = 0.0f;
    for (int h = lane; h < Hd; h += 32) s += xr[h] * gr[h];
    #pragma unroll
    for (int o = 16; o; o >>= 1) s += __shfl_xor_sync(0xFFFFFFFFu, s, o);

    __shared__ float sc[Ed];
    if (lane == 0) sc[warp] = s;
    __syncthreads();

    if (threadIdx.x < Ed && write_logits)
        out_logits[t * Ed + threadIdx.x] = sc[threadIdx.x];

    if (threadIdx.x == 0) {
        float v[Ed];
        #pragma unroll
        for (int e = 0; e < Ed; e++) v[e] = sc[e];

        // ---- top-1 ----
        int   s1 = 0; float m1 = v[0];
        #pragma unroll
        for (int e = 1; e < Ed; e++) if (v[e] > m1) { m1 = v[e]; s1 = e; }
        float Z1 = 0.0f;
        #pragma unroll
        for (int e = 0; e < Ed; e++) {
            float factor = fmaxf(fabsf(v[e]), m1);
            bool  mask   = (m1 - v[e]) / factor > 0.02f;   // 2*jitter_eps
            if (!mask) Z1 += expf(v[e] - m1);
        }
        float mult1 = 1.0f / Z1;   // exp(v[s1]-m1)=1

        // ---- top-2 (top-1 masked out) ----
        int   s2 = -1; float m2 = -INFINITY;
        #pragma unroll
        for (int e = 0; e < Ed; e++) if (e != s1 && v[e] > m2) { m2 = v[e]; s2 = e; }
        float Z2 = 0.0f;
        #pragma unroll
        for (int e = 0; e < Ed; e++) {
            if (e == s1) continue;                          // masked_scores[s1] = -inf
            float factor = fmaxf(fabsf(v[e]), m2);
            bool  mask   = (m2 - v[e]) / factor > 0.02f;
            if (!mask) Z2 += expf(v[e] - m2);
        }
        float mult2 = 1.0f / Z2;

        g_sel [t * 2 + 0] = s1;  g_sel [t * 2 + 1] = s2;
        g_mult[t * 2 + 0] = mult1; g_mult[t * 2 + 1] = mult2;
    }
}

// ---------------- kernel 2: scatter tokens to per-expert lists -------------
__global__ void scatter_kernel() {
    int t = blockIdx.x * 256 + threadIdx.x;
    if (t >= T) return;
    #pragma unroll
    for (int k = 0; k < 2; k++) {
        int e = g_sel[t * 2 + k];
        int p = atomicAdd(&g_cnt[e], 1);
        g_tok[e * T + p] = t;
        g_pw [e * T + p] = g_mult[t * 2 + k];
    }
}

// ---------------- kernel 3: inter = silu(x@w1^T) * (x@w3^T) per expert -----
// grid: (Fd/TN, Ed * (T/TM)), block 256
__global__ __launch_bounds__(256) void ffn1_kernel(
    const float* __restrict__ x,
    const float* __restrict__ w1,
    const float* __restrict__ w3)
{
    int e   = blockIdx.y >> 4;         // T/TM = 16 m-tiles per expert
    int mt  = blockIdx.y & 15;
    int cnt = g_cnt[e];
    int m0  = mt * TM;
    if (m0 >= cnt) return;
    int f0  = blockIdx.x * TN;

    __shared__ __align__(16) float xs [TK][TM];
    __shared__ __align__(16) float w1s[TK][TN];
    __shared__ __align__(16) float w3s[TK][TN];
    __shared__ int toks[TM];

    int tid = threadIdx.x;
    if (tid < TM) {
        int idx = m0 + tid;
        toks[tid] = (idx < cnt) ? g_tok[e * T + idx] : g_tok[e * T];
    }
    __syncthreads();

    int lr = tid >> 2;             // load row 0..63
    int lc = (tid & 3) * 4;        // load k quad: 0,4,8,12
    int tx = tid & 15;             // compute col group
    int ty = tid >> 4;             // compute row group

    const float* w1e = w1 + (size_t)e * Fd * Hd;
    const float* w3e = w3 + (size_t)e * Fd * Hd;
    const float* xrow  = x   + (size_t)toks[lr] * Hd + lc;
    const float* w1row = w1e + (size_t)(f0 + lr) * Hd + lc;
    const float* w3row = w3e + (size_t)(f0 + lr) * Hd + lc;

    float acc1[4][4] = {}, acc3[4][4] = {};

    for (int k0 = 0; k0 < Hd; k0 += TK) {
        float4 xa = *(const float4*)(xrow  + k0);
        float4 b1 = *(const float4*)(w1row + k0);
        float4 b3 = *(const float4*)(w3row + k0);
        __syncthreads();   // previous compute done
        xs [lc + 0][lr] = xa.x; xs [lc + 1][lr] = xa.y; xs [lc + 2][lr] = xa.z; xs [lc + 3][lr] = xa.w;
        w1s[lc + 0][lr] = b1.x; w1s[lc + 1][lr] = b1.y; w1s[lc + 2][lr] = b1.z; w1s[lc + 3][lr] = b1.w;
        w3s[lc + 0][lr] = b3.x; w3s[lc + 1][lr] = b3.y; w3s[lc + 2][lr] = b3.z; w3s[lc + 3][lr] = b3.w;
        __syncthreads();
        #pragma unroll
        for (int k = 0; k < TK; k++) {
            float4 a = *(const float4*)&xs [k][ty * 4];
            float4 u = *(const float4*)&w1s[k][tx * 4];
            float4 w = *(const float4*)&w3s[k][tx * 4];
            float av[4] = {a.x, a.y, a.z, a.w};
            float uv[4] = {u.x, u.y, u.z, u.w};
            float wv[4] = {w.x, w.y, w.z, w.w};
            #pragma unroll
            for (int i = 0; i < 4; i++)
                #pragma unroll
                for (int j = 0; j < 4; j++) {
                    acc1[i][j] = fmaf(av[i], uv[j], acc1[i][j]);
                    acc3[i][j] = fmaf(av[i], wv[j], acc3[i][j]);
                }
        }
    }

    // epilogue: silu(h1)*h3 -> g_inter, float4 stores
    #pragma unroll
    for (int i = 0; i < 4; i++) {
        size_t slot = (size_t)e * T + m0 + ty * 4 + i;
        float4 o;
        float h1, h3;
        h1 = acc1[i][0]; h3 = acc3[i][0]; o.x = h1 / (1.0f + expf(-h1)) * h3;
        h1 = acc1[i][1]; h3 = acc3[i][1]; o.y = h1 / (1.0f + expf(-h1)) * h3;
        h1 = acc1[i][2]; h3 = acc3[i][2]; o.z = h1 / (1.0f + expf(-h1)) * h3;
        h1 = acc1[i][3]; h3 = acc3[i][3]; o.w = h1 / (1.0f + expf(-h1)) * h3;
        *(float4*)(&g_inter[slot * Fd + f0 + tx * 4]) = o;
    }
}

// ---------------- kernel 4: out[t] += w * (inter @ w2^T) --------------------
// grid: (Hd/TN, Ed * (T/TM)), block 256
__global__ __launch_bounds__(256) void ffn2_kernel(
    const float* __restrict__ w2, float* __restrict__ out)
{
    int e   = blockIdx.y >> 4;
    int mt  = blockIdx.y & 15;
    int cnt = g_cnt[e];
    int m0  = mt * TM;
    if (m0 >= cnt) return;
    int h0  = blockIdx.x * TN;

    __shared__ __align__(16) float as[TK][TM];
    __shared__ __align__(16) float bs[TK][TN];
    __shared__ int   toks[TM];
    __shared__ float pws [TM];

    int tid = threadIdx.x;
    if (tid < TM) {
        int idx = m0 + tid;
        toks[tid] = (idx < cnt) ? g_tok[e * T + idx] : 0;
        pws [tid] = (idx < cnt) ? g_pw [e * T + idx] : 0.0f;
    }
    __syncthreads();

    int lr = tid >> 2;
    int lc = (tid & 3) * 4;
    int tx = tid & 15;
    int ty = tid >> 4;

    const float* arow = &g_inter[((size_t)e * T + m0 + lr) * Fd + lc];
    const float* brow = w2 + ((size_t)e * Hd + h0 + lr) * Fd + lc;

    float acc[4][4] = {};

    for (int k0 = 0; k0 < Fd; k0 += TK) {
        float4 aa = *(const float4*)(arow + k0);
        float4 bb = *(const float4*)(brow + k0);
        __syncthreads();
        as[lc + 0][lr] = aa.x; as[lc + 1][lr] = aa.y; as[lc + 2][lr] = aa.z; as[lc + 3][lr] = aa.w;
        bs[lc + 0][lr] = bb.x; bs[lc + 1][lr] = bb.y; bs[lc + 2][lr] = bb.z; bs[lc + 3][lr] = bb.w;
        __syncthreads();
        #pragma unroll
        for (int k = 0; k < TK; k++) {
            float4 a = *(const float4*)&as[k][ty * 4];
            float4 b = *(const float4*)&bs[k][tx * 4];
            float av[4] = {a.x, a.y, a.z, a.w};
            float bv[4] = {b.x, b.y, b.z, b.w};
            #pragma unroll
            for (int i = 0; i < 4; i++)
                #pragma unroll
                for (int j = 0; j < 4; j++)
                    acc[i][j] = fmaf(av[i], bv[j], acc[i][j]);
        }
    }

    // epilogue: weighted atomic accumulate into final output
    #pragma unroll
    for (int i = 0; i < 4; i++) {
        int m = m0 + ty * 4 + i;
        if (m < cnt) {
            int   t   = toks[ty * 4 + i];
            float wgt = pws [ty * 4 + i];
            float* orow = out + (size_t)t * Hd + h0 + tx * 4;
            #pragma unroll
            for (int j = 0; j < 4; j++)
                atomicAdd(&orow[j], wgt * acc[i][j]);
        }
    }
}

// ---------------- launch --------------------------------------------------
extern "C" void kernel_launch(void* const* d_in, const int* in_sizes, int n_in,
                              void* d_out, int out_size)
{
    const float* x  = (const float*)d_in[0];   // hidden_states [1,1024,1024]
    const float* gw = (const float*)d_in[1];   // gate_w [8,1024]
    const float* w1 = (const float*)d_in[2];   // w1 [8,2048,1024]
    const float* w2 = (const float*)d_in[3];   // w2 [8,1024,2048]
    const float* w3 = (const float*)d_in[4];   // w3 [8,2048,1024]
    float* out = (float*)d_out;

    int write_logits = (out_size >= T * Hd + T * Ed) ? 1 : 0;
    float* out_logits = out + (size_t)T * Hd;

    zero_kernel   <<<(T * Hd) / 256, 256>>>(out);
    router_kernel <<<T, 256>>>(x, gw, out_logits, write_logits);
    scatter_kernel<<<T / 256, 256>>>();

    dim3 g1(Fd / TN, Ed * (T / TM));
    ffn1_kernel<<<g1, 256>>>(x, w1, w3);

    dim3 g2(Hd / TN, Ed * (T / TM));
    ffn2_kernel<<<g2, 256>>>(w2, out);
}

// round 2
// speedup vs baseline: 1.1898x; 1.1898x over previous
#include <cuda_runtime.h>
#include <mma.h>
#include <math.h>

using namespace nvcuda;

#define T  1024
#define Hd 1024
#define Fd 2048
#define Ed 8

#define BM 128
#define BN 64
#define BK 32
#define KPAD 40   // BK + 8 pad (multiple of 4 for wmma ldm)

// ---------------- scratch (device globals; no runtime allocation) ----------
__device__ float g_inter[(size_t)Ed * T * Fd];  // 64 MB
__device__ int   g_tok[Ed * T];
__device__ float g_pw[Ed * T];
__device__ int   g_cnt[Ed];
__device__ int   g_sel[T * 2];
__device__ float g_mult[T * 2];

// round fp32 -> tf32 (RN) so HMMA truncation is lossless afterwards
__device__ __forceinline__ float tf32r(float x) {
    float r;
    asm("cvt.rna.tf32.f32 %0, %1;" : "=f"(r) : "f"(x));
    return r;
}

#define ST4TF(dst, v) { (dst)[0]=tf32r((v).x); (dst)[1]=tf32r((v).y); (dst)[2]=tf32r((v).z); (dst)[3]=tf32r((v).w); }

// ---------------- kernel 0: zero output + counters --------------------------
__global__ void zero_kernel(float* __restrict__ out) {
    int i = blockIdx.x * 256 + threadIdx.x;
    out[i] = 0.0f;
    if (i < Ed) g_cnt[i] = 0;
}

// ---------------- kernel 1: router GEMV + sparsemixer (eval) ---------------
__global__ __launch_bounds__(256) void router_kernel(
    const float* __restrict__ x, const float* __restrict__ gw,
    float* __restrict__ out_logits, int write_logits)
{
    int t    = blockIdx.x;
    int warp = threadIdx.x >> 5;
    int lane = threadIdx.x & 31;

    const float* xr = x  + (size_t)t * Hd;
    const float* gr = gw + (size_t)warp * Hd;
    float s = 0.0f;
    for (int h = lane; h < Hd; h += 32) s += xr[h] * gr[h];
    #pragma unroll
    for (int o = 16; o; o >>= 1) s += __shfl_xor_sync(0xFFFFFFFFu, s, o);

    __shared__ float sc[Ed];
    if (lane == 0) sc[warp] = s;
    __syncthreads();

    if (threadIdx.x < Ed && write_logits)
        out_logits[t * Ed + threadIdx.x] = sc[threadIdx.x];

    if (threadIdx.x == 0) {
        float v[Ed];
        #pragma unroll
        for (int e = 0; e < Ed; e++) v[e] = sc[e];

        int   s1 = 0; float m1 = v[0];
        #pragma unroll
        for (int e = 1; e < Ed; e++) if (v[e] > m1) { m1 = v[e]; s1 = e; }
        float Z1 = 0.0f;
        #pragma unroll
        for (int e = 0; e < Ed; e++) {
            float factor = fmaxf(fabsf(v[e]), m1);
            bool  mask   = (m1 - v[e]) / factor > 0.02f;
            if (!mask) Z1 += expf(v[e] - m1);
        }
        float mult1 = 1.0f / Z1;

        int   s2 = -1; float m2 = -INFINITY;
        #pragma unroll
        for (int e = 0; e < Ed; e++) if (e != s1 && v[e] > m2) { m2 = v[e]; s2 = e; }
        float Z2 = 0.0f;
        #pragma unroll
        for (int e = 0; e < Ed; e++) {
            if (e == s1) continue;
            float factor = fmaxf(fabsf(v[e]), m2);
            bool  mask   = (m2 - v[e]) / factor > 0.02f;
            if (!mask) Z2 += expf(v[e] - m2);
        }
        float mult2 = 1.0f / Z2;

        g_sel [t * 2 + 0] = s1;    g_sel [t * 2 + 1] = s2;
        g_mult[t * 2 + 0] = mult1; g_mult[t * 2 + 1] = mult2;
    }
}

// ---------------- kernel 2: scatter tokens to per-expert lists -------------
__global__ void scatter_kernel() {
    int t = blockIdx.x * 256 + threadIdx.x;
    if (t >= T) return;
    #pragma unroll
    for (int k = 0; k < 2; k++) {
        int e = g_sel[t * 2 + k];
        int p = atomicAdd(&g_cnt[e], 1);
        g_tok[e * T + p] = t;
        g_pw [e * T + p] = g_mult[t * 2 + k];
    }
}

// ---------------- kernel 3: inter = silu(x@w1^T) * (x@w3^T), tf32 wmma ------
// grid: (Fd/BN, Ed * (T/BM)), block 256 (8 warps, 4x2 warp grid, 32x32/warp)
__global__ __launch_bounds__(256, 1) void ffn1_kernel(
    const float* __restrict__ x,
    const float* __restrict__ w1,
    const float* __restrict__ w3)
{
    int e   = blockIdx.y >> 3;         // T/BM = 8 m-tiles per expert
    int mt  = blockIdx.y & 7;
    int cnt = g_cnt[e];
    int m0  = mt * BM;
    if (m0 >= cnt) return;
    int f0  = blockIdx.x * BN;

    __shared__ int toks[BM];
    __shared__ __align__(16) float As [BM][KPAD];
    __shared__ __align__(16) float B1s[BN][KPAD];
    __shared__ __align__(16) float B3s[BN][KPAD];

    int tid = threadIdx.x;
    if (tid < BM) {
        int idx = m0 + tid;
        toks[tid] = (idx < cnt) ? g_tok[e * T + idx] : g_tok[e * T];
    }
    __syncthreads();

    int arow = tid >> 3;            // 0..31
    int ac   = (tid & 7) * 4;       // 0,4,...,28

    const float* w1e = w1 + (size_t)e * Fd * Hd;
    const float* w3e = w3 + (size_t)e * Fd * Hd;

    const float* xp0 = x + (size_t)toks[arow      ] * Hd + ac;
    const float* xp1 = x + (size_t)toks[arow + 32 ] * Hd + ac;
    const float* xp2 = x + (size_t)toks[arow + 64 ] * Hd + ac;
    const float* xp3 = x + (size_t)toks[arow + 96 ] * Hd + ac;
    const float* u0p = w1e + (size_t)(f0 + arow     ) * Hd + ac;
    const float* u1p = w1e + (size_t)(f0 + arow + 32) * Hd + ac;
    const float* v0p = w3e + (size_t)(f0 + arow     ) * Hd + ac;
    const float* v1p = w3e + (size_t)(f0 + arow + 32) * Hd + ac;

    wmma::fragment<wmma::matrix_a, 16,16,8, wmma::precision::tf32, wmma::row_major> fa[2];
    wmma::fragment<wmma::matrix_b, 16,16,8, wmma::precision::tf32, wmma::col_major> fb1[2], fb3[2];
    wmma::fragment<wmma::accumulator, 16,16,8, float> acc1[2][2], acc3[2][2];
    #pragma unroll
    for (int i = 0; i < 2; i++)
        #pragma unroll
        for (int j = 0; j < 2; j++) {
            wmma::fill_fragment(acc1[i][j], 0.0f);
            wmma::fill_fragment(acc3[i][j], 0.0f);
        }

    int wid = tid >> 5;
    int wm  = wid >> 1;     // 0..3
    int wn  = wid & 1;      // 0..1

    for (int k0 = 0; k0 < Hd; k0 += BK) {
        float4 a0 = *(const float4*)(xp0 + k0);
        float4 a1 = *(const float4*)(xp1 + k0);
        float4 a2 = *(const float4*)(xp2 + k0);
        float4 a3 = *(const float4*)(xp3 + k0);
        float4 u0 = *(const float4*)(u0p + k0);
        float4 u1 = *(const float4*)(u1p + k0);
        float4 v0 = *(const float4*)(v0p + k0);
        float4 v1 = *(const float4*)(v1p + k0);
        __syncthreads();   // previous stage compute done
        ST4TF(&As [arow     ][ac], a0);
        ST4TF(&As [arow + 32][ac], a1);
        ST4TF(&As [arow + 64][ac], a2);
        ST4TF(&As [arow + 96][ac], a3);
        ST4TF(&B1s[arow     ][ac], u0);
        ST4TF(&B1s[arow + 32][ac], u1);
        ST4TF(&B3s[arow     ][ac], v0);
        ST4TF(&B3s[arow + 32][ac], v1);
        __syncthreads();

        #pragma unroll
        for (int ks = 0; ks < BK; ks += 8) {
            wmma::load_matrix_sync(fa[0], &As[wm * 32     ][ks], KPAD);
            wmma::load_matrix_sync(fa[1], &As[wm * 32 + 16][ks], KPAD);
            wmma::load_matrix_sync(fb1[0], &B1s[wn * 32     ][ks], KPAD);
            wmma::load_matrix_sync(fb1[1], &B1s[wn * 32 + 16][ks], KPAD);
            wmma::load_matrix_sync(fb3[0], &B3s[wn * 32     ][ks], KPAD);
            wmma::load_matrix_sync(fb3[1], &B3s[wn * 32 + 16][ks], KPAD);
            #pragma unroll
            for (int i = 0; i < 2; i++)
                #pragma unroll
                for (int j = 0; j < 2; j++) {
                    wmma::mma_sync(acc1[i][j], fa[i], fb1[j], acc1[i][j]);
                    wmma::mma_sync(acc3[i][j], fa[i], fb3[j], acc3[i][j]);
                }
        }
    }

    // epilogue: silu(h1)*h3, store row-major to g_inter
    float* obase = &g_inter[((size_t)e * T + m0) * Fd + f0];
    #pragma unroll
    for (int i = 0; i < 2; i++)
        #pragma unroll
        for (int j = 0; j < 2; j++) {
            #pragma unroll
            for (int el = 0; el < acc1[i][j].num_elements; el++) {
                float h1 = acc1[i][j].x[el];
                float h3 = acc3[i][j].x[el];
                acc1[i][j].x[el] = h1 / (1.0f + expf(-h1)) * h3;
            }
            wmma::store_matrix_sync(
                obase + (size_t)(wm * 32 + i * 16) * Fd + wn * 32 + j * 16,
                acc1[i][j], Fd, wmma::mem_row_major);
        }
}

// ---------------- kernel 4: out[t] += pw * (inter @ w2^T), tf32 wmma --------
// grid: (Hd/BN, Ed * (T/BM)), block 256
#define OPAD 68
__global__ __launch_bounds__(256, 1) void ffn2_kernel(
    const float* __restrict__ w2, float* __restrict__ out)
{
    int e   = blockIdx.y >> 3;
    int mt  = blockIdx.y & 7;
    int cnt = g_cnt[e];
    int m0  = mt * BM;
    if (m0 >= cnt) return;
    int h0  = blockIdx.x * BN;

    __shared__ int   toks[BM];
    __shared__ float pws [BM];
    // pool: during loop = As[BM][KPAD] + Bs[BN][KPAD] (7680 f); after = Os[BM][OPAD] (8704 f)
    __shared__ __align__(16) float pool[BM * OPAD];
    float (*As)[KPAD] = (float (*)[KPAD])pool;
    float (*Bs)[KPAD] = (float (*)[KPAD])(pool + BM * KPAD);

    int tid = threadIdx.x;
    if (tid < BM) {
        int idx = m0 + tid;
        toks[tid] = (idx < cnt) ? g_tok[e * T + idx] : 0;
        pws [tid] = (idx < cnt) ? g_pw [e * T + idx] : 0.0f;
    }
    __syncthreads();

    int arow = tid >> 3;
    int ac   = (tid & 7) * 4;

    float pw0 = pws[arow];
    float pw1 = pws[arow + 32];
    float pw2 = pws[arow + 64];
    float pw3 = pws[arow + 96];

    const float* ap0 = &g_inter[((size_t)e * T + m0 + arow     ) * Fd + ac];
    const float* ap1 = &g_inter[((size_t)e * T + m0 + arow + 32) * Fd + ac];
    const float* ap2 = &g_inter[((size_t)e * T + m0 + arow + 64) * Fd + ac];
    const float* ap3 = &g_inter[((size_t)e * T + m0 + arow + 96) * Fd + ac];
    const float* bp0 = w2 + ((size_t)e * Hd + h0 + arow     ) * Fd + ac;
    const float* bp1 = w2 + ((size_t)e * Hd + h0 + arow + 32) * Fd + ac;

    wmma::fragment<wmma::matrix_a, 16,16,8, wmma::precision::tf32, wmma::row_major> fa[2];
    wmma::fragment<wmma::matrix_b, 16,16,8, wmma::precision::tf32, wmma::col_major> fb[2];
    wmma::fragment<wmma::accumulator, 16,16,8, float> acc[2][2];
    #pragma unroll
    for (int i = 0; i < 2; i++)
        #pragma unroll
        for (int j = 0; j < 2; j++) wmma::fill_fragment(acc[i][j], 0.0f);

    int wid = tid >> 5;
    int wm  = wid >> 1;
    int wn  = wid & 1;

    for (int k0 = 0; k0 < Fd; k0 += BK) {
        float4 a0 = *(const float4*)(ap0 + k0);
        float4 a1 = *(const float4*)(ap1 + k0);
        float4 a2 = *(const float4*)(ap2 + k0);
        float4 a3 = *(const float4*)(ap3 + k0);
        float4 b0 = *(const float4*)(bp0 + k0);
        float4 b1 = *(const float4*)(bp1 + k0);
        // fold routing weight into A
        a0.x *= pw0; a0.y *= pw0; a0.z *= pw0; a0.w *= pw0;
        a1.x *= pw1; a1.y *= pw1; a1.z *= pw1; a1.w *= pw1;
        a2.x *= pw2; a2.y *= pw2; a2.z *= pw2; a2.w *= pw2;
        a3.x *= pw3; a3.y *= pw3; a3.z *= pw3; a3.w *= pw3;
        __syncthreads();
        ST4TF(&As[arow     ][ac], a0);
        ST4TF(&As[arow + 32][ac], a1);
        ST4TF(&As[arow + 64][ac], a2);
        ST4TF(&As[arow + 96][ac], a3);
        ST4TF(&Bs[arow     ][ac], b0);
        ST4TF(&Bs[arow + 32][ac], b1);
        __syncthreads();

        #pragma unroll
        for (int ks = 0; ks < BK; ks += 8) {
            wmma::load_matrix_sync(fa[0], &As[wm * 32     ][ks], KPAD);
            wmma::load_matrix_sync(fa[1], &As[wm * 32 + 16][ks], KPAD);
            wmma::load_matrix_sync(fb[0], &Bs[wn * 32     ][ks], KPAD);
            wmma::load_matrix_sync(fb[1], &Bs[wn * 32 + 16][ks], KPAD);
            #pragma unroll
            for (int i = 0; i < 2; i++)
                #pragma unroll
                for (int j = 0; j < 2; j++)
                    wmma::mma_sync(acc[i][j], fa[i], fb[j], acc[i][j]);
        }
    }

    // epilogue: stage to smem, then atomicAdd into token rows
    __syncthreads();
    #pragma unroll
    for (int i = 0; i < 2; i++)
        #pragma unroll
        for (int j = 0; j < 2; j++)
            wmma::store_matrix_sync(
                pool + (size_t)(wm * 32 + i * 16) * OPAD + wn * 32 + j * 16,
                acc[i][j], OPAD, wmma::mem_row_major);
    __syncthreads();

    for (int idx = tid; idx < BM * BN; idx += 256) {
        int r = idx >> 6;          // 0..127
        int c = idx & 63;          // 0..63
        if (m0 + r < cnt)
            atomicAdd(&out[(size_t)toks[r] * Hd + h0 + c], pool[r * OPAD + c]);
    }
}

// ---------------- launch ----------------------------------------------------
extern "C" void kernel_launch(void* const* d_in, const int* in_sizes, int n_in,
                              void* d_out, int out_size)
{
    const float* x  = (const float*)d_in[0];
    const float* gw = (const float*)d_in[1];
    const float* w1 = (const float*)d_in[2];
    const float* w2 = (const float*)d_in[3];
    const float* w3 = (const float*)d_in[4];
    float* out = (float*)d_out;

    int write_logits = (out_size >= T * Hd + T * Ed) ? 1 : 0;
    float* out_logits = out + (size_t)T * Hd;

    zero_kernel   <<<(T * Hd) / 256, 256>>>(out);
    router_kernel <<<T, 256>>>(x, gw, out_logits, write_logits);
    scatter_kernel<<<T / 256, 256>>>();

    dim3 g1(Fd / BN, Ed * (T / BM));
    ffn1_kernel<<<g1, 256>>>(x, w1, w3);

    dim3 g2(Hd / BN, Ed * (T / BM));
    ffn2_kernel<<<g2, 256>>>(w2, out);
}

// round 3
// speedup vs baseline: 1.3238x; 1.1126x over previous
#include <cuda_runtime.h>
#include <mma.h>
#include <math.h>

using namespace nvcuda;

#define T  1024
#define Hd 1024
#define Fd 2048
#define Ed 8

#define BM 128
#define BN 64
#define BK 16
#define KP 20      // BK + 4 pad (mult of 4 elems for wmma ldm; 16B-aligned rows)
#define OPAD 68

// ---------------- scratch (device globals; no runtime allocation) ----------
__device__ float g_inter[(size_t)Ed * T * Fd];
__device__ int   g_tok[Ed * T];
__device__ float g_pw[Ed * T];
__device__ int   g_cnt[Ed];
__device__ int   g_sel[T * 2];
__device__ float g_mult[T * 2];

__device__ __forceinline__ float tf32r(float x) {
    float r;
    asm("cvt.rna.tf32.f32 %0, %1;" : "=f"(r) : "f"(x));
    return r;
}

__device__ __forceinline__ void cp16(float* s, const float* g) {
    unsigned a = (unsigned)__cvta_generic_to_shared(s);
    asm volatile("cp.async.cg.shared.global [%0], [%1], 16;" :: "r"(a), "l"(g));
}
#define CP_COMMIT() asm volatile("cp.async.commit_group;" ::)
#define CP_WAIT1()  asm volatile("cp.async.wait_group 1;" ::)

// ---------------- kernel 0: zero output + counters --------------------------
__global__ void zero_kernel(float* __restrict__ out) {
    int i = blockIdx.x * 256 + threadIdx.x;
    out[i] = 0.0f;
    if (i < Ed) g_cnt[i] = 0;
}

// ---------------- kernel 1: router GEMV + sparsemixer (eval) ---------------
__global__ __launch_bounds__(256) void router_kernel(
    const float* __restrict__ x, const float* __restrict__ gw,
    float* __restrict__ out_logits, int write_logits)
{
    int t    = blockIdx.x;
    int warp = threadIdx.x >> 5;
    int lane = threadIdx.x & 31;

    const float* xr = x  + (size_t)t * Hd;
    const float* gr = gw + (size_t)warp * Hd;
    float s = 0.0f;
    for (int h = lane; h < Hd; h += 32) s += xr[h] * gr[h];
    #pragma unroll
    for (int o = 16; o; o >>= 1) s += __shfl_xor_sync(0xFFFFFFFFu, s, o);

    __shared__ float sc[Ed];
    if (lane == 0) sc[warp] = s;
    __syncthreads();

    if (threadIdx.x < Ed && write_logits)
        out_logits[t * Ed + threadIdx.x] = sc[threadIdx.x];

    if (threadIdx.x == 0) {
        float v[Ed];
        #pragma unroll
        for (int e = 0; e < Ed; e++) v[e] = sc[e];

        int   s1 = 0; float m1 = v[0];
        #pragma unroll
        for (int e = 1; e < Ed; e++) if (v[e] > m1) { m1 = v[e]; s1 = e; }
        float Z1 = 0.0f;
        #pragma unroll
        for (int e = 0; e < Ed; e++) {
            float factor = fmaxf(fabsf(v[e]), m1);
            bool  mask   = (m1 - v[e]) / factor > 0.02f;
            if (!mask) Z1 += expf(v[e] - m1);
        }
        float mult1 = 1.0f / Z1;

        int   s2 = -1; float m2 = -INFINITY;
        #pragma unroll
        for (int e = 0; e < Ed; e++) if (e != s1 && v[e] > m2) { m2 = v[e]; s2 = e; }
        float Z2 = 0.0f;
        #pragma unroll
        for (int e = 0; e < Ed; e++) {
            if (e == s1) continue;
            float factor = fmaxf(fabsf(v[e]), m2);
            bool  mask   = (m2 - v[e]) / factor > 0.02f;
            if (!mask) Z2 += expf(v[e] - m2);
        }
        float mult2 = 1.0f / Z2;

        g_sel [t * 2 + 0] = s1;    g_sel [t * 2 + 1] = s2;
        g_mult[t * 2 + 0] = mult1; g_mult[t * 2 + 1] = mult2;
    }
}

// ---------------- kernel 2: scatter tokens to per-expert lists -------------
__global__ void scatter_kernel() {
    int t = blockIdx.x * 256 + threadIdx.x;
    if (t >= T) return;
    #pragma unroll
    for (int k = 0; k < 2; k++) {
        int e = g_sel[t * 2 + k];
        int p = atomicAdd(&g_cnt[e], 1);
        g_tok[e * T + p] = t;
        g_pw [e * T + p] = g_mult[t * 2 + k];
    }
}

// ---------------- kernel 3: inter = silu(x@w1^T)*(x@w3^T), pipelined tf32 ---
// grid (Fd/BN, Ed*8), block 512 (16 warps, 4x4, 32x16 tile per warp, 2 gemms)
__global__ __launch_bounds__(512) void ffn1_kernel(
    const float* __restrict__ x,
    const float* __restrict__ w1,
    const float* __restrict__ w3)
{
    int e   = blockIdx.y >> 3;
    int mt  = blockIdx.y & 7;
    int cnt = g_cnt[e];
    int m0  = mt * BM;
    if (m0 >= cnt) return;
    int f0  = blockIdx.x * BN;

    __shared__ int toks[BM];
    __shared__ __align__(16) float As [2 * BM * KP];
    __shared__ __align__(16) float B1s[2 * BN * KP];
    __shared__ __align__(16) float B3s[2 * BN * KP];

    int tid = threadIdx.x;
    if (tid < BM) {
        int i = m0 + tid;
        toks[tid] = (i < cnt) ? g_tok[e * T + i] : g_tok[e * T];
    }
    __syncthreads();

    int lr = tid >> 2;             // 0..127 (A row)
    int lk = (tid & 3) * 4;        // k quad
    int br = (tid & 255) >> 2;     // 0..63 (B row)

    const float* ag = x + (size_t)toks[lr] * Hd + lk;
    const float* wsel = (tid < 256) ? w1 : w3;
    const float* bg = wsel + (size_t)e * Fd * Hd + (size_t)(f0 + br) * Hd + lk;
    float* a_sm = As + lr * KP + lk;
    float* b_sm = ((tid < 256) ? B1s : B3s) + br * KP + lk;

    // prologue: stage 0
    cp16(a_sm, ag);
    cp16(b_sm, bg);
    CP_COMMIT();

    wmma::fragment<wmma::matrix_a, 16,16,8, wmma::precision::tf32, wmma::row_major> fa[2];
    wmma::fragment<wmma::matrix_b, 16,16,8, wmma::precision::tf32, wmma::col_major> fb1, fb3;
    wmma::fragment<wmma::accumulator, 16,16,8, float> acc1[2], acc3[2];
    wmma::fill_fragment(acc1[0], 0.f); wmma::fill_fragment(acc1[1], 0.f);
    wmma::fill_fragment(acc3[0], 0.f); wmma::fill_fragment(acc3[1], 0.f);

    int wid = tid >> 5;
    int wm  = wid >> 2;    // 0..3 -> 32 rows
    int wn  = wid & 3;     // 0..3 -> 16 cols

    int buf = 0;
    for (int k0 = 0; k0 < Hd; k0 += BK) {
        if (k0 + BK < Hd) {
            int nb = buf ^ 1;
            cp16(a_sm + nb * BM * KP, ag + k0 + BK);
            cp16(b_sm + nb * BN * KP, bg + k0 + BK);
        }
        CP_COMMIT();
        CP_WAIT1();
        __syncthreads();

        const float* Ab  = As  + buf * BM * KP;
        const float* B1b = B1s + buf * BN * KP;
        const float* B3b = B3s + buf * BN * KP;
        #pragma unroll
        for (int ks = 0; ks < BK; ks += 8) {
            wmma::load_matrix_sync(fa[0], Ab + (wm * 32     ) * KP + ks, KP);
            wmma::load_matrix_sync(fa[1], Ab + (wm * 32 + 16) * KP + ks, KP);
            wmma::load_matrix_sync(fb1,   B1b + (wn * 16) * KP + ks, KP);
            wmma::load_matrix_sync(fb3,   B3b + (wn * 16) * KP + ks, KP);
            #pragma unroll
            for (int q = 0; q < 4; q++) {
                fa[0].x[q] = tf32r(fa[0].x[q]);
                fa[1].x[q] = tf32r(fa[1].x[q]);
                fb1.x[q]   = tf32r(fb1.x[q]);
                fb3.x[q]   = tf32r(fb3.x[q]);
            }
            wmma::mma_sync(acc1[0], fa[0], fb1, acc1[0]);
            wmma::mma_sync(acc1[1], fa[1], fb1, acc1[1]);
            wmma::mma_sync(acc3[0], fa[0], fb3, acc3[0]);
            wmma::mma_sync(acc3[1], fa[1], fb3, acc3[1]);
        }
        __syncthreads();
        buf ^= 1;
    }

    float* ob = &g_inter[((size_t)e * T + m0 + wm * 32) * Fd + f0 + wn * 16];
    #pragma unroll
    for (int i = 0; i < 2; i++) {
        #pragma unroll
        for (int el = 0; el < acc1[i].num_elements; el++) {
            float h1 = acc1[i].x[el], h3 = acc3[i].x[el];
            acc1[i].x[el] = h1 / (1.0f + expf(-h1)) * h3;
        }
        wmma::store_matrix_sync(ob + (size_t)i * 16 * Fd, acc1[i], Fd, wmma::mem_row_major);
    }
}

// ---------------- kernel 4: out[t] += pw*(inter@w2^T), pipelined tf32 -------
// grid (Hd/BN, Ed*8), block 512
__global__ __launch_bounds__(512) void ffn2_kernel(
    const float* __restrict__ w2, float* __restrict__ out)
{
    int e   = blockIdx.y >> 3;
    int mt  = blockIdx.y & 7;
    int cnt = g_cnt[e];
    int m0  = mt * BM;
    if (m0 >= cnt) return;
    int h0  = blockIdx.x * BN;

    __shared__ int   toks[BM];
    __shared__ float pws [BM];
    // pool: loop phase As(2*128*20=5120) + Bs(2*64*20=2560) = 7680 floats;
    //       epilogue phase Os[128][OPAD] = 8704 floats
    __shared__ __align__(16) float pool[BM * OPAD];
    float* As = pool;
    float* Bs = pool + 2 * BM * KP;

    int tid = threadIdx.x;
    if (tid < BM) {
        int i = m0 + tid;
        toks[tid] = (i < cnt) ? g_tok[e * T + i] : 0;
        pws [tid] = (i < cnt) ? g_pw [e * T + i] : 0.0f;
    }
    __syncthreads();

    int lr = tid >> 2;
    int lk = (tid & 3) * 4;
    int br = (tid & 255) >> 2;
    bool doB = (tid < 256);

    const float* ag = &g_inter[((size_t)e * T + m0 + lr) * Fd + lk];
    const float* bg = w2 + ((size_t)e * Hd + h0 + br) * Fd + lk;
    float* a_sm = As + lr * KP + lk;
    float* b_sm = Bs + br * KP + lk;

    cp16(a_sm, ag);
    if (doB) cp16(b_sm, bg);
    CP_COMMIT();

    wmma::fragment<wmma::matrix_a, 16,16,8, wmma::precision::tf32, wmma::row_major> fa[2];
    wmma::fragment<wmma::matrix_b, 16,16,8, wmma::precision::tf32, wmma::col_major> fb;
    wmma::fragment<wmma::accumulator, 16,16,8, float> acc[2];
    wmma::fill_fragment(acc[0], 0.f); wmma::fill_fragment(acc[1], 0.f);

    int wid = tid >> 5;
    int wm  = wid >> 2;
    int wn  = wid & 3;

    int buf = 0;
    for (int k0 = 0; k0 < Fd; k0 += BK) {
        if (k0 + BK < Fd) {
            int nb = buf ^ 1;
            cp16(a_sm + nb * BM * KP, ag + k0 + BK);
            if (doB) cp16(b_sm + nb * BN * KP, bg + k0 + BK);
        }
        CP_COMMIT();
        CP_WAIT1();
        __syncthreads();

        const float* Ab = As + buf * BM * KP;
        const float* Bb = Bs + buf * BN * KP;
        #pragma unroll
        for (int ks = 0; ks < BK; ks += 8) {
            wmma::load_matrix_sync(fa[0], Ab + (wm * 32     ) * KP + ks, KP);
            wmma::load_matrix_sync(fa[1], Ab + (wm * 32 + 16) * KP + ks, KP);
            wmma::load_matrix_sync(fb,    Bb + (wn * 16) * KP + ks, KP);
            #pragma unroll
            for (int q = 0; q < 4; q++) {
                fa[0].x[q] = tf32r(fa[0].x[q]);
                fa[1].x[q] = tf32r(fa[1].x[q]);
                fb.x[q]    = tf32r(fb.x[q]);
            }
            wmma::mma_sync(acc[0], fa[0], fb, acc[0]);
            wmma::mma_sync(acc[1], fa[1], fb, acc[1]);
        }
        __syncthreads();
        buf ^= 1;
    }

    // epilogue: stage to smem (reuse pool), scale by pw, atomicAdd
    __syncthreads();
    #pragma unroll
    for (int i = 0; i < 2; i++)
        wmma::store_matrix_sync(
            pool + (size_t)(wm * 32 + i * 16) * OPAD + wn * 16,
            acc[i], OPAD, wmma::mem_row_major);
    __syncthreads();

    for (int idx = tid; idx < BM * BN; idx += 512) {
        int r = idx >> 6;
        int c = idx & 63;
        if (m0 + r < cnt)
            atomicAdd(&out[(size_t)toks[r] * Hd + h0 + c], pws[r] * pool[r * OPAD + c]);
    }
}

// ---------------- launch ----------------------------------------------------
extern "C" void kernel_launch(void* const* d_in, const int* in_sizes, int n_in,
                              void* d_out, int out_size)
{
    const float* x  = (const float*)d_in[0];
    const float* gw = (const float*)d_in[1];
    const float* w1 = (const float*)d_in[2];
    const float* w2 = (const float*)d_in[3];
    const float* w3 = (const float*)d_in[4];
    float* out = (float*)d_out;

    int write_logits = (out_size >= T * Hd + T * Ed) ? 1 : 0;
    float* out_logits = out + (size_t)T * Hd;

    zero_kernel   <<<(T * Hd) / 256, 256>>>(out);
    router_kernel <<<T, 256>>>(x, gw, out_logits, write_logits);
    scatter_kernel<<<T / 256, 256>>>();

    dim3 g1(Fd / BN, Ed * 8);
    ffn1_kernel<<<g1, 512>>>(x, w1, w3);

    dim3 g2(Hd / BN, Ed * 8);
    ffn2_kernel<<<g2, 512>>>(w2, out);
}